// round 12
// baseline (speedup 1.0000x reference)
#include <cuda_runtime.h>
#include <cuda_fp16.h>
#include <cstdint>

#define S 4096
#define DM 1024
#define H 16
#define HD 64
#define WIN 512
#define NK 3072

// ---------------- device scratch (fp16 frag-major, PAIR-PACKED B) ----------
// g_xc : a-frag [mt(256)][k16(64)][lane][4]
// g_wc : b-frag [np16(192)][k16(64)][lane][4]  u32s={evn8 r0,evn8 r1,odd r0,odd r1}
// g_q2 : a-frag [h][mt(256)][d16(4)][lane][4]
// g_k2 : b-frag [h][kp16(256)][d16(4)][lane][4]   (n=keys pair-packed, k=d)
// g_v2 : b-frag [h][t(64)][dp16(4)][k16(4)][lane][4] (n=d pair-packed, k=keys)
__device__ uint32_t g_xc[S * DM / 2];
__device__ uint32_t g_wc[DM * NK / 2];
__device__ uint32_t g_q2[H * S * HD / 2];
__device__ uint32_t g_k2[H * S * HD / 2];
__device__ uint32_t g_v2[H * S * HD / 2];

// ---------------- helpers ---------------------------------------------------
__device__ __forceinline__ uint32_t h2(float lo, float hi) {
    half2 h = __floats2half2_rn(lo, hi);
    return *(uint32_t*)&h;
}
__device__ __forceinline__ uint32_t smem_u32(const void* p) {
    uint32_t a;
    asm("{ .reg .u64 t; cvta.to.shared.u64 t, %1; cvt.u32.u64 %0, t; }"
        : "=r"(a) : "l"(p));
    return a;
}
__device__ __forceinline__ void cp16(uint32_t dst, const void* src) {
    asm volatile("cp.async.cg.shared.global [%0], [%1], 16;" :: "r"(dst), "l"(src));
}
__device__ __forceinline__ void cp_commit() {
    asm volatile("cp.async.commit_group;" ::: "memory");
}
__device__ __forceinline__ void cp_wait0() { asm volatile("cp.async.wait_group 0;" ::: "memory"); }
__device__ __forceinline__ void cp_wait1() { asm volatile("cp.async.wait_group 1;" ::: "memory"); }
__device__ __forceinline__ void cp_wait2() { asm volatile("cp.async.wait_group 2;" ::: "memory"); }
__device__ __forceinline__ void mma16816(float* c, const uint32_t* a,
                                         uint32_t b0, uint32_t b1) {
    asm volatile(
        "mma.sync.aligned.m16n8k16.row.col.f32.f16.f16.f32 "
        "{%0,%1,%2,%3}, {%4,%5,%6,%7}, {%8,%9}, {%0,%1,%2,%3};"
        : "+f"(c[0]), "+f"(c[1]), "+f"(c[2]), "+f"(c[3])
        : "r"(a[0]), "r"(a[1]), "r"(a[2]), "r"(a[3]), "r"(b0), "r"(b1));
}

// ---------------- prep ------------------------------------------------------
__global__ __launch_bounds__(256) void prep_x(const float* __restrict__ x) {
    int row = blockIdx.x;
    int k0 = threadIdx.x * 4;
    float4 v = *(const float4*)&x[(size_t)row * DM + k0];
    uint32_t ha = h2(v.x, v.y);
    uint32_t hb = h2(v.z, v.w);
    int base = ((row >> 4) * 64 + (k0 >> 4)) * 128;
    int r = ((row >> 3) & 1) + 2 * ((k0 >> 3) & 1);
    int lane = (row & 7) * 4 + ((k0 & 7) >> 1);
    g_xc[base + lane * 4 + r] = ha;
    g_xc[base + (lane + 1) * 4 + r] = hb;
}
__global__ __launch_bounds__(256) void prep_w(const float* __restrict__ w) {
    int g = blockIdx.x * 256 + threadIdx.x;
    int k0 = 2 * (g / 768);
    int n0 = 4 * (g % 768);
    float4 v0 = *(const float4*)&w[(size_t)k0 * NK + n0];
    float4 v1 = *(const float4*)&w[(size_t)(k0 + 1) * NK + n0];
    float a0[4] = {v0.x, v0.y, v0.z, v0.w};
    float a1[4] = {v1.x, v1.y, v1.z, v1.w};
    int k16 = k0 >> 4;
    int lcp = (k0 & 7) >> 1;
    int reg = (k0 >> 3) & 1;
#pragma unroll
    for (int t = 0; t < 4; t++) {
        int n = n0 + t;
        g_wc[((n >> 4) * 64 + k16) * 128 + ((n & 7) * 4 + lcp) * 4 + ((n >> 3) & 1) * 2 + reg]
            = h2(a0[t], a1[t]);
    }
}

// ---------------- fp16 KQV GEMM: 128x128, BK=32, 4 stages -------------------
#define GSTAGE_U 4096                         // A 2048 + B 2048
#define GNSTAGES 4
#define GEMM_SMEM (GNSTAGES * GSTAGE_U * 4)   // 64 KB

__device__ __forceinline__ void g_load_stage(uint32_t sb, int st, int kt, int tid,
                                             int mt0, int npb) {
    uint32_t ab = sb + st * (GSTAGE_U * 4);
    uint32_t bb = ab + 2048 * 4;
#pragma unroll
    for (int u = 0; u < 2; u++) {                  // A: 512 uint4
        int c = tid + u * 256;
        int blk = c >> 5, cb = c & 31;             // 16 blocks = 8mt x 2k16
        cp16(ab + (blk * 32 + cb) * 16,
             g_xc + (size_t)((mt0 + (blk >> 1)) * 64 + kt * 2 + (blk & 1)) * 128 + cb * 4);
    }
#pragma unroll
    for (int u = 0; u < 2; u++) {                  // B: 512 uint4, 16 blocks = 8np x 2k16
        int c = tid + u * 256;
        int blk = c >> 5, cb = c & 31;
        cp16(bb + (blk * 32 + cb) * 16,
             g_wc + (size_t)((npb + (blk >> 1)) * 64 + kt * 2 + (blk & 1)) * 128 + cb * 4);
    }
}

__global__ __launch_bounds__(256) void kqv_gemm_mma() {
    extern __shared__ __align__(16) uint8_t smem_raw[];
    uint32_t sb = smem_u32(smem_raw);
    const int tid = threadIdx.x;
    const int warp = tid >> 5, lane = tid & 31;
    const int lr = lane >> 2, lc = lane & 3;
    const int wm = warp >> 1, wn = warp & 1;
    const int n0 = blockIdx.x * 128;
    const int m0 = blockIdx.y * 128;
    const int mt0 = blockIdx.y * 8;
    const int npb = blockIdx.x * 8;

    float c[2][8][4];
#pragma unroll
    for (int i = 0; i < 2; i++)
#pragma unroll
        for (int j = 0; j < 8; j++)
#pragma unroll
            for (int t = 0; t < 4; t++) c[i][j][t] = 0.f;

#pragma unroll
    for (int s = 0; s < GNSTAGES - 1; s++) {
        g_load_stage(sb, s, s, tid, mt0, npb);
        cp_commit();
    }
    cp_wait2();
    __syncthreads();

    for (int kt = 0; kt < 32; kt++) {
        int st = kt & (GNSTAGES - 1);
        const uint32_t* As = (const uint32_t*)(smem_raw + st * (GSTAGE_U * 4));
        const uint32_t* Bs = As + 2048;
        uint32_t a[2][2][4], b[4][2][4];
#pragma unroll
        for (int i = 0; i < 2; i++)
#pragma unroll
            for (int kk = 0; kk < 2; kk++) {
                uint4 v = *(const uint4*)&As[((wm * 2 + i) * 2 + kk) * 128 + lane * 4];
                a[i][kk][0] = v.x; a[i][kk][1] = v.y; a[i][kk][2] = v.z; a[i][kk][3] = v.w;
            }
#pragma unroll
        for (int jp = 0; jp < 4; jp++)
#pragma unroll
            for (int kk = 0; kk < 2; kk++) {
                uint4 v = *(const uint4*)&Bs[((wn * 4 + jp) * 2 + kk) * 128 + lane * 4];
                b[jp][kk][0] = v.x; b[jp][kk][1] = v.y; b[jp][kk][2] = v.z; b[jp][kk][3] = v.w;
            }
#pragma unroll
        for (int kk = 0; kk < 2; kk++)
#pragma unroll
            for (int i = 0; i < 2; i++)
#pragma unroll
                for (int jp = 0; jp < 4; jp++) {
                    mma16816(c[i][2 * jp + 0], a[i][kk], b[jp][kk][0], b[jp][kk][1]);
                    mma16816(c[i][2 * jp + 1], a[i][kk], b[jp][kk][2], b[jp][kk][3]);
                }
        __syncthreads();
        int nk = kt + GNSTAGES - 1;
        if (nk < 32) g_load_stage(sb, nk & (GNSTAGES - 1), nk, tid, mt0, npb);
        cp_commit();
        cp_wait2();
        __syncthreads();
    }

    // ---- epilogue ----
    const int gc0 = n0 + wn * 64;
    const int chunk = gc0 >> 10;
    const int h = (gc0 & 1023) >> 6;
    const int mbase = m0 + wm * 32;

#pragma unroll
    for (int i = 0; i < 2; i++) {
#pragma unroll
        for (int j = 0; j < 8; j++) {
            float v0 = c[i][j][0], v1 = c[i][j][1], v2 = c[i][j][2], v3 = c[i][j][3];
            int r = mbase + i * 16 + lr;
            if (chunk == 1) {                     // Q : a-frag (unchanged)
                int base = ((h * 256 + (r >> 4)) * 4 + (j >> 1)) * 128
                           + (lr * 4 + lc) * 4 + 2 * (j & 1);
                g_q2[base + 0] = h2(v0, v1);
                g_q2[base + 1] = h2(v2, v3);
            } else if (chunk == 0) {              // K : pair-packed b-frag
                int base = ((h * 256 + (r >> 4)) * 4 + (j >> 1)) * 128
                           + (lr * 4 + lc) * 4 + (j & 1);
                g_k2[base + 0] = h2(v0, v1);      // key r   (bit 0)
                g_k2[base + 2] = h2(v2, v3);      // key r+8 (bit 1)
            } else {                              // V : pair-packed b-frag
                half* gv = (half*)g_v2;
#pragma unroll
                for (int rb = 0; rb < 2; rb++) {
                    int m = r + rb * 8;
                    float va = rb ? v2 : v0, vb = rb ? v3 : v1;
                    int blkh = (((h * 64 + (m >> 6)) * 4 + (j >> 1)) * 4 + ((m >> 4) & 3)) * 256;
                    int sub = rb * 2 + (lr & 1);  // reg*2 + halfsub
                    int l0 = 8 * lc + (lr >> 1);  // lane for d
                    gv[blkh + (l0 * 4 + (j & 1) * 2) * 2 + sub] = __float2half_rn(va);
                    gv[blkh + ((l0 + 4) * 4 + (j & 1) * 2) * 2 + sub] = __float2half_rn(vb);
                }
            }
        }
    }
}

// ---------------------------------------------------------------------------
// fp16 flash attention: 64 queries x head, 4 warps, 4 blocks/SM, paired LDS.
// ---------------------------------------------------------------------------
#define KV_U(s) ((s) * 4096)
#define ATTN_SMEM (2 * 4096 * 4)             // 32 KB
#define SCL 0.03125f

__device__ __forceinline__ void a_load_kv(uint32_t sb, int s, int kt, int tid,
                                          const uint32_t* __restrict__ kb,
                                          const uint32_t* __restrict__ vb) {
    uint32_t kd = sb + KV_U(s) * 4;
    uint32_t vd = kd + 2048 * 4;
    const uint32_t* kg = kb + (size_t)kt * 2048;
    const uint32_t* vg = vb + (size_t)kt * 2048;
#pragma unroll
    for (int u = 0; u < 4; u++) {
        int c = tid + u * 128;
        cp16(kd + c * 16, kg + c * 4);
        cp16(vd + c * 16, vg + c * 4);
    }
}

__global__ __launch_bounds__(128, 4) void attn_tc(float* __restrict__ out) {
    extern __shared__ __align__(16) uint8_t smem_raw[];
    uint32_t* smu = (uint32_t*)smem_raw;
    uint32_t sb = smem_u32(smem_raw);

    const int tid = threadIdx.x;
    const int w = tid >> 5, lane = tid & 31;
    const int lr = lane >> 2, lc = lane & 3;
    const int qt = blockIdx.x;
    const int h = blockIdx.y;
    const int q0 = qt * 64;

    const float slope = exp2f(-0.5f * (float)(h + 1));
    const uint32_t* __restrict__ kbh = g_k2 + (size_t)h * 256 * 512;
    const uint32_t* __restrict__ vbh = g_v2 + (size_t)h * 64 * 2048;

    const int kt0 = (qt >= 8) ? (qt - 8) : 0;
    const int kt1 = qt;

    a_load_kv(sb, 0, kt0, tid, kbh, vbh);
    cp_commit();

    uint32_t qa[4][4];
    {
        const uint32_t* qb = g_q2 + (size_t)((h * 256 + qt * 4 + w) * 4) * 128;
#pragma unroll
        for (int d16 = 0; d16 < 4; d16++) {
            uint4 v = *(const uint4*)&qb[d16 * 128 + lane * 4];
            qa[d16][0] = v.x; qa[d16][1] = v.y; qa[d16][2] = v.z; qa[d16][3] = v.w;
        }
    }

    float o[8][4];
    float m0r = -1e30f, m1r = -1e30f, l0 = 0.f, l1 = 0.f;
#pragma unroll
    for (int dt = 0; dt < 8; dt++)
#pragma unroll
        for (int t = 0; t < 4; t++) o[dt][t] = 0.f;

    const int i0 = q0 + w * 16 + lr;
    const int i1 = i0 + 8;
    const float s8 = slope * 8.f;

    for (int kt = kt0; kt <= kt1; kt++) {
        int st = (kt - kt0) & 1;
        if (kt < kt1) {
            a_load_kv(sb, st ^ 1, kt + 1, tid, kbh, vbh);
            cp_commit();
            cp_wait1();
        } else {
            cp_wait0();
        }
        __syncthreads();

        const uint32_t* Ks = smu + KV_U(st);
        const uint32_t* Vs = Ks + 2048;
        const int kb = kt * 64;

        // ---- S = Q K^T : paired K loads ----
        float sc[8][4];
#pragma unroll
        for (int nt = 0; nt < 8; nt++)
#pragma unroll
            for (int t = 0; t < 4; t++) sc[nt][t] = 0.f;
#pragma unroll
        for (int d16 = 0; d16 < 4; d16++) {
#pragma unroll
            for (int np = 0; np < 4; np++) {
                uint4 v = *(const uint4*)&Ks[(np * 4 + d16) * 128 + lane * 4];
                mma16816(sc[2 * np + 0], qa[d16], v.x, v.y);
                mma16816(sc[2 * np + 1], qa[d16], v.z, v.w);
            }
        }

        // ---- bias/mask + online softmax ----
        const bool full = (kt >= qt - 7) && (kt <= qt - 1);
        float mx0 = -3e38f, mx1 = -3e38f;
        if (full) {
            float bias = slope * (float)(kb + 2 * lc - i0);
#pragma unroll
            for (int nt = 0; nt < 8; nt++) {
                sc[nt][0] = fmaf(sc[nt][0], SCL, bias);
                sc[nt][1] = fmaf(sc[nt][1], SCL, bias + slope);
                sc[nt][2] = fmaf(sc[nt][2], SCL, bias - s8);
                sc[nt][3] = fmaf(sc[nt][3], SCL, bias - s8 + slope);
                mx0 = fmaxf(mx0, fmaxf(sc[nt][0], sc[nt][1]));
                mx1 = fmaxf(mx1, fmaxf(sc[nt][2], sc[nt][3]));
                bias += s8;
            }
        } else {
#pragma unroll
            for (int nt = 0; nt < 8; nt++) {
                int j0 = kb + nt * 8 + 2 * lc;
                int d00 = i0 - j0;
                sc[nt][0] = (d00 >= 0 && d00 <= WIN)
                                ? fmaf(sc[nt][0], SCL, slope * (float)(-d00)) : -3e38f;
                int d01 = d00 - 1;
                sc[nt][1] = (d01 >= 0 && d01 <= WIN)
                                ? fmaf(sc[nt][1], SCL, slope * (float)(-d01)) : -3e38f;
                int d10 = i1 - j0;
                sc[nt][2] = (d10 >= 0 && d10 <= WIN)
                                ? fmaf(sc[nt][2], SCL, slope * (float)(-d10)) : -3e38f;
                int d11 = d10 - 1;
                sc[nt][3] = (d11 >= 0 && d11 <= WIN)
                                ? fmaf(sc[nt][3], SCL, slope * (float)(-d11)) : -3e38f;
                mx0 = fmaxf(mx0, fmaxf(sc[nt][0], sc[nt][1]));
                mx1 = fmaxf(mx1, fmaxf(sc[nt][2], sc[nt][3]));
            }
        }
        mx0 = fmaxf(mx0, __shfl_xor_sync(0xffffffffu, mx0, 1));
        mx0 = fmaxf(mx0, __shfl_xor_sync(0xffffffffu, mx0, 2));
        mx1 = fmaxf(mx1, __shfl_xor_sync(0xffffffffu, mx1, 1));
        mx1 = fmaxf(mx1, __shfl_xor_sync(0xffffffffu, mx1, 2));

        float mn0 = fmaxf(m0r, mx0), mn1 = fmaxf(m1r, mx1);
        float al0 = __expf(m0r - mn0), al1 = __expf(m1r - mn1);
        m0r = mn0; m1r = mn1;

        // ---- exp + row-sum + in-register P a-frags ----
        uint32_t pa[4][4];
        float rs0 = 0.f, rs1 = 0.f;
#pragma unroll
        for (int nt = 0; nt < 8; nt++) {
            float p00 = __expf(sc[nt][0] - mn0);
            float p01 = __expf(sc[nt][1] - mn0);
            float p10 = __expf(sc[nt][2] - mn1);
            float p11 = __expf(sc[nt][3] - mn1);
            rs0 += p00 + p01;
            rs1 += p10 + p11;
            pa[nt >> 1][(nt & 1) * 2 + 0] = h2(p00, p01);
            pa[nt >> 1][(nt & 1) * 2 + 1] = h2(p10, p11);
        }
        rs0 += __shfl_xor_sync(0xffffffffu, rs0, 1);
        rs0 += __shfl_xor_sync(0xffffffffu, rs0, 2);
        rs1 += __shfl_xor_sync(0xffffffffu, rs1, 1);
        rs1 += __shfl_xor_sync(0xffffffffu, rs1, 2);
        l0 = l0 * al0 + rs0;
        l1 = l1 * al1 + rs1;
#pragma unroll
        for (int dt = 0; dt < 8; dt++) {
            o[dt][0] *= al0; o[dt][1] *= al0;
            o[dt][2] *= al1; o[dt][3] *= al1;
        }

        // ---- O += P V : paired V loads ----
#pragma unroll
        for (int k16 = 0; k16 < 4; k16++) {
#pragma unroll
            for (int dp = 0; dp < 4; dp++) {
                uint4 v = *(const uint4*)&Vs[(dp * 4 + k16) * 128 + lane * 4];
                mma16816(o[2 * dp + 0], pa[k16], v.x, v.y);
                mma16816(o[2 * dp + 1], pa[k16], v.z, v.w);
            }
        }
        __syncthreads();
    }

    // ---- normalize + write ----
    float inv0 = 1.f / l0, inv1 = 1.f / l1;
    float* o0 = out + (size_t)i0 * DM + h * HD;
    float* o1 = out + (size_t)i1 * DM + h * HD;
#pragma unroll
    for (int dt = 0; dt < 8; dt++) {
        *(float2*)&o0[dt * 8 + 2 * lc] = make_float2(o[dt][0] * inv0, o[dt][1] * inv0);
        *(float2*)&o1[dt * 8 + 2 * lc] = make_float2(o[dt][2] * inv1, o[dt][3] * inv1);
    }
}

// ---------------------------------------------------------------------------
extern "C" void kernel_launch(void* const* d_in, const int* in_sizes, int n_in,
                              void* d_out, int out_size) {
    const float* x = (const float*)d_in[0];
    const float* w = (const float*)d_in[1];
    if (n_in >= 2 && in_sizes[0] == DM * NK && in_sizes[1] == S * DM) {
        const float* t = x; x = w; w = t;
    }
    float* out = (float*)d_out;

    static int attr_set = 0;
    if (!attr_set) {
        cudaFuncSetAttribute(kqv_gemm_mma, cudaFuncAttributeMaxDynamicSharedMemorySize,
                             GEMM_SMEM);
        cudaFuncSetAttribute(attn_tc, cudaFuncAttributeMaxDynamicSharedMemorySize,
                             ATTN_SMEM);
        attr_set = 1;
    }

    prep_x<<<4096, 256>>>(x);
    prep_w<<<1536, 256>>>(w);

    dim3 ggrid(NK / 128, S / 128);
    kqv_gemm_mma<<<ggrid, 256, GEMM_SMEM>>>();

    dim3 agrid(S / 64, H);
    attn_tc<<<agrid, 128, ATTN_SMEM>>>(out);
}

// round 14
// speedup vs baseline: 1.0312x; 1.0312x over previous
#include <cuda_runtime.h>
#include <cuda_fp16.h>
#include <cstdint>

#define S 4096
#define DM 1024
#define H 16
#define HD 64
#define WIN 512
#define NK 3072

// ---------------- device scratch (fp16 frag-major, PAIR-PACKED B) ----------
__device__ uint32_t g_xc[S * DM / 2];
__device__ uint32_t g_wc[DM * NK / 2];
__device__ uint32_t g_q2[H * S * HD / 2];
__device__ uint32_t g_k2[H * S * HD / 2];
__device__ uint32_t g_v2[H * S * HD / 2];

// ---------------- helpers ---------------------------------------------------
__device__ __forceinline__ uint32_t h2(float lo, float hi) {
    half2 h = __floats2half2_rn(lo, hi);
    return *(uint32_t*)&h;
}
__device__ __forceinline__ float ex2f(float x) {
    float r;
    asm("ex2.approx.f32 %0, %1;" : "=f"(r) : "f"(x));
    return r;
}
__device__ __forceinline__ uint32_t smem_u32(const void* p) {
    uint32_t a;
    asm("{ .reg .u64 t; cvta.to.shared.u64 t, %1; cvt.u32.u64 %0, t; }"
        : "=r"(a) : "l"(p));
    return a;
}
__device__ __forceinline__ void cp16(uint32_t dst, const void* src) {
    asm volatile("cp.async.cg.shared.global [%0], [%1], 16;" :: "r"(dst), "l"(src));
}
__device__ __forceinline__ void cp_commit() {
    asm volatile("cp.async.commit_group;" ::: "memory");
}
__device__ __forceinline__ void cp_wait0() { asm volatile("cp.async.wait_group 0;" ::: "memory"); }
__device__ __forceinline__ void cp_wait1() { asm volatile("cp.async.wait_group 1;" ::: "memory"); }
__device__ __forceinline__ void cp_wait2() { asm volatile("cp.async.wait_group 2;" ::: "memory"); }
__device__ __forceinline__ void mma16816(float* c, const uint32_t* a,
                                         uint32_t b0, uint32_t b1) {
    asm volatile(
        "mma.sync.aligned.m16n8k16.row.col.f32.f16.f16.f32 "
        "{%0,%1,%2,%3}, {%4,%5,%6,%7}, {%8,%9}, {%0,%1,%2,%3};"
        : "+f"(c[0]), "+f"(c[1]), "+f"(c[2]), "+f"(c[3])
        : "r"(a[0]), "r"(a[1]), "r"(a[2]), "r"(a[3]), "r"(b0), "r"(b1));
}

// ---------------- prep ------------------------------------------------------
__global__ __launch_bounds__(256) void prep_x(const float* __restrict__ x) {
    int row = blockIdx.x;
    int k0 = threadIdx.x * 4;
    float4 v = *(const float4*)&x[(size_t)row * DM + k0];
    uint32_t ha = h2(v.x, v.y);
    uint32_t hb = h2(v.z, v.w);
    int base = ((row >> 4) * 64 + (k0 >> 4)) * 128;
    int r = ((row >> 3) & 1) + 2 * ((k0 >> 3) & 1);
    int lane = (row & 7) * 4 + ((k0 & 7) >> 1);
    g_xc[base + lane * 4 + r] = ha;
    g_xc[base + (lane + 1) * 4 + r] = hb;
}
__global__ __launch_bounds__(256) void prep_w(const float* __restrict__ w) {
    int g = blockIdx.x * 256 + threadIdx.x;
    int k0 = 2 * (g / 768);
    int n0 = 4 * (g % 768);
    float4 v0 = *(const float4*)&w[(size_t)k0 * NK + n0];
    float4 v1 = *(const float4*)&w[(size_t)(k0 + 1) * NK + n0];
    float a0[4] = {v0.x, v0.y, v0.z, v0.w};
    float a1[4] = {v1.x, v1.y, v1.z, v1.w};
    int k16 = k0 >> 4;
    int lcp = (k0 & 7) >> 1;
    int reg = (k0 >> 3) & 1;
#pragma unroll
    for (int t = 0; t < 4; t++) {
        int n = n0 + t;
        g_wc[((n >> 4) * 64 + k16) * 128 + ((n & 7) * 4 + lcp) * 4 + ((n >> 3) & 1) * 2 + reg]
            = h2(a0[t], a1[t]);
    }
}

// ---------------- fp16 KQV GEMM: 128x128, BK=32, 4 stages, 1 sync/iter ------
#define GSTAGE_U 4096
#define GNSTAGES 4
#define GEMM_SMEM (GNSTAGES * GSTAGE_U * 4)

__device__ __forceinline__ void g_load_stage(uint32_t sb, int st, int kt, int tid,
                                             int mt0, int npb) {
    uint32_t ab = sb + st * (GSTAGE_U * 4);
    uint32_t bb = ab + 2048 * 4;
#pragma unroll
    for (int u = 0; u < 2; u++) {
        int c = tid + u * 256;
        int blk = c >> 5, cb = c & 31;
        cp16(ab + (blk * 32 + cb) * 16,
             g_xc + (size_t)((mt0 + (blk >> 1)) * 64 + kt * 2 + (blk & 1)) * 128 + cb * 4);
    }
#pragma unroll
    for (int u = 0; u < 2; u++) {
        int c = tid + u * 256;
        int blk = c >> 5, cb = c & 31;
        cp16(bb + (blk * 32 + cb) * 16,
             g_wc + (size_t)((npb + (blk >> 1)) * 64 + kt * 2 + (blk & 1)) * 128 + cb * 4);
    }
}

__global__ __launch_bounds__(256) void kqv_gemm_mma() {
    extern __shared__ __align__(16) uint8_t smem_raw[];
    uint32_t sb = smem_u32(smem_raw);
    const int tid = threadIdx.x;
    const int warp = tid >> 5, lane = tid & 31;
    const int lr = lane >> 2, lc = lane & 3;
    const int wm = warp >> 1, wn = warp & 1;
    const int n0 = blockIdx.x * 128;
    const int m0 = blockIdx.y * 128;
    const int mt0 = blockIdx.y * 8;
    const int npb = blockIdx.x * 8;

    float c[2][8][4];
#pragma unroll
    for (int i = 0; i < 2; i++)
#pragma unroll
        for (int j = 0; j < 8; j++)
#pragma unroll
            for (int t = 0; t < 4; t++) c[i][j][t] = 0.f;

#pragma unroll
    for (int s = 0; s < GNSTAGES - 1; s++) {
        g_load_stage(sb, s, s, tid, mt0, npb);
        cp_commit();
    }
    cp_wait2();
    __syncthreads();

    for (int kt = 0; kt < 32; kt++) {
        int st = kt & (GNSTAGES - 1);
        const uint32_t* As = (const uint32_t*)(smem_raw + st * (GSTAGE_U * 4));
        const uint32_t* Bs = As + 2048;
        uint32_t a[2][2][4], b[4][2][4];
#pragma unroll
        for (int i = 0; i < 2; i++)
#pragma unroll
            for (int kk = 0; kk < 2; kk++) {
                uint4 v = *(const uint4*)&As[((wm * 2 + i) * 2 + kk) * 128 + lane * 4];
                a[i][kk][0] = v.x; a[i][kk][1] = v.y; a[i][kk][2] = v.z; a[i][kk][3] = v.w;
            }
#pragma unroll
        for (int jp = 0; jp < 4; jp++)
#pragma unroll
            for (int kk = 0; kk < 2; kk++) {
                uint4 v = *(const uint4*)&Bs[((wn * 4 + jp) * 2 + kk) * 128 + lane * 4];
                b[jp][kk][0] = v.x; b[jp][kk][1] = v.y; b[jp][kk][2] = v.z; b[jp][kk][3] = v.w;
            }
#pragma unroll
        for (int kk = 0; kk < 2; kk++)
#pragma unroll
            for (int i = 0; i < 2; i++)
#pragma unroll
                for (int jp = 0; jp < 4; jp++) {
                    mma16816(c[i][2 * jp + 0], a[i][kk], b[jp][kk][0], b[jp][kk][1]);
                    mma16816(c[i][2 * jp + 1], a[i][kk], b[jp][kk][2], b[jp][kk][3]);
                }
        int nk = kt + GNSTAGES - 1;
        if (nk < 32) g_load_stage(sb, nk & (GNSTAGES - 1), nk, tid, mt0, npb);
        cp_commit();
        cp_wait2();
        __syncthreads();
    }

    // ---- epilogue ----
    const int gc0 = n0 + wn * 64;
    const int chunk = gc0 >> 10;
    const int h = (gc0 & 1023) >> 6;
    const int mbase = m0 + wm * 32;

#pragma unroll
    for (int i = 0; i < 2; i++) {
#pragma unroll
        for (int j = 0; j < 8; j++) {
            float v0 = c[i][j][0], v1 = c[i][j][1], v2 = c[i][j][2], v3 = c[i][j][3];
            int r = mbase + i * 16 + lr;
            if (chunk == 1) {                     // Q : a-frag
                int base = ((h * 256 + (r >> 4)) * 4 + (j >> 1)) * 128
                           + (lr * 4 + lc) * 4 + 2 * (j & 1);
                g_q2[base + 0] = h2(v0, v1);
                g_q2[base + 1] = h2(v2, v3);
            } else if (chunk == 0) {              // K : pair-packed b-frag
                int base = ((h * 256 + (r >> 4)) * 4 + (j >> 1)) * 128
                           + (lr * 4 + lc) * 4 + (j & 1);
                g_k2[base + 0] = h2(v0, v1);
                g_k2[base + 2] = h2(v2, v3);
            } else {                              // V : pair-packed b-frag
                half* gv = (half*)g_v2;
#pragma unroll
                for (int rb = 0; rb < 2; rb++) {
                    int m = r + rb * 8;
                    float va = rb ? v2 : v0, vb = rb ? v3 : v1;
                    int blkh = (((h * 64 + (m >> 6)) * 4 + (j >> 1)) * 4 + ((m >> 4) & 3)) * 256;
                    int sub = rb * 2 + (lr & 1);
                    int l0 = 8 * lc + (lr >> 1);
                    gv[blkh + (l0 * 4 + (j & 1) * 2) * 2 + sub] = __float2half_rn(va);
                    gv[blkh + ((l0 + 4) * 4 + (j & 1) * 2) * 2 + sub] = __float2half_rn(vb);
                }
            }
        }
    }
}

// ---------------------------------------------------------------------------
// fp16 flash attention: 64 queries x head, 4 warps, 4 blocks/SM.
// log2-domain softmax, descending key tiles, ones-column MMA for row sums.
// ---------------------------------------------------------------------------
#define KV_U(s) ((s) * 4096)
#define ATTN_SMEM (2 * 4096 * 4)
#define LOG2E 1.44269504f
#define SCL2 (0.03125f * LOG2E)
#define ONESH2 0x3C003C00u

__device__ __forceinline__ void a_load_kv(uint32_t sb, int s, int kt, int tid,
                                          const uint32_t* __restrict__ kb,
                                          const uint32_t* __restrict__ vb) {
    uint32_t kd = sb + KV_U(s) * 4;
    uint32_t vd = kd + 2048 * 4;
    const uint32_t* kg = kb + (size_t)kt * 2048;
    const uint32_t* vg = vb + (size_t)kt * 2048;
#pragma unroll
    for (int u = 0; u < 4; u++) {
        int c = tid + u * 128;
        cp16(kd + c * 16, kg + c * 4);
        cp16(vd + c * 16, vg + c * 4);
    }
}

__global__ __launch_bounds__(128, 4) void attn_tc(float* __restrict__ out) {
    extern __shared__ __align__(16) uint8_t smem_raw[];
    uint32_t* smu = (uint32_t*)smem_raw;
    uint32_t sb = smem_u32(smem_raw);

    const int tid = threadIdx.x;
    const int w = tid >> 5, lane = tid & 31;
    const int lr = lane >> 2, lc = lane & 3;
    const int qt = blockIdx.x;
    const int h = blockIdx.y;
    const int q0 = qt * 64;

    const float slope2 = exp2f(-0.5f * (float)(h + 1)) * LOG2E;  // log2-domain slope
    const uint32_t* __restrict__ kbh = g_k2 + (size_t)h * 256 * 512;
    const uint32_t* __restrict__ vbh = g_v2 + (size_t)h * 64 * 2048;

    const int kt0 = (qt >= 8) ? (qt - 8) : 0;
    const int kt1 = qt;

    a_load_kv(sb, 0, kt1, tid, kbh, vbh);     // diagonal tile first
    cp_commit();

    uint32_t qa[4][4];
    {
        const uint32_t* qb = g_q2 + (size_t)((h * 256 + qt * 4 + w) * 4) * 128;
#pragma unroll
        for (int d16 = 0; d16 < 4; d16++) {
            uint4 v = *(const uint4*)&qb[d16 * 128 + lane * 4];
            qa[d16][0] = v.x; qa[d16][1] = v.y; qa[d16][2] = v.z; qa[d16][3] = v.w;
        }
    }

    float o[8][4], oe[4];
    float m0r = -1e30f, m1r = -1e30f;
#pragma unroll
    for (int dt = 0; dt < 8; dt++)
#pragma unroll
        for (int t = 0; t < 4; t++) o[dt][t] = 0.f;
#pragma unroll
    for (int t = 0; t < 4; t++) oe[t] = 0.f;

    const int i0 = q0 + w * 16 + lr;
    const int i1 = i0 + 8;
    const float s8 = slope2 * 8.f;

    for (int it = 0; it <= kt1 - kt0; it++) {
        const int kt = kt1 - it;                   // descending
        const int st = it & 1;
        if (kt > kt0) {
            a_load_kv(sb, st ^ 1, kt - 1, tid, kbh, vbh);
            cp_commit();
            cp_wait1();
        } else {
            cp_wait0();
        }
        __syncthreads();

        const uint32_t* Ks = smu + KV_U(st);
        const uint32_t* Vs = Ks + 2048;
        const int kb = kt * 64;

        // ---- S = Q K^T ----
        float sc[8][4];
#pragma unroll
        for (int nt = 0; nt < 8; nt++)
#pragma unroll
            for (int t = 0; t < 4; t++) sc[nt][t] = 0.f;
#pragma unroll
        for (int d16 = 0; d16 < 4; d16++) {
#pragma unroll
            for (int np = 0; np < 4; np++) {
                uint4 v = *(const uint4*)&Ks[(np * 4 + d16) * 128 + lane * 4];
                mma16816(sc[2 * np + 0], qa[d16], v.x, v.y);
                mma16816(sc[2 * np + 1], qa[d16], v.z, v.w);
            }
        }

        // ---- bias/mask (log2 domain) + max ----
        const bool full = (kt >= qt - 7) && (kt <= qt - 1);
        float mx0 = -3e38f, mx1 = -3e38f;
        if (full) {
            float bias = slope2 * (float)(kb + 2 * lc - i0);
#pragma unroll
            for (int nt = 0; nt < 8; nt++) {
                sc[nt][0] = fmaf(sc[nt][0], SCL2, bias);
                sc[nt][1] = fmaf(sc[nt][1], SCL2, bias + slope2);
                sc[nt][2] = fmaf(sc[nt][2], SCL2, bias - s8);
                sc[nt][3] = fmaf(sc[nt][3], SCL2, bias - s8 + slope2);
                mx0 = fmaxf(mx0, fmaxf(sc[nt][0], sc[nt][1]));
                mx1 = fmaxf(mx1, fmaxf(sc[nt][2], sc[nt][3]));
                bias += s8;
            }
        } else {
#pragma unroll
            for (int nt = 0; nt < 8; nt++) {
                int j0 = kb + nt * 8 + 2 * lc;
                int d00 = i0 - j0;
                sc[nt][0] = (d00 >= 0 && d00 <= WIN)
                                ? fmaf(sc[nt][0], SCL2, slope2 * (float)(-d00)) : -3e38f;
                int d01 = d00 - 1;
                sc[nt][1] = (d01 >= 0 && d01 <= WIN)
                                ? fmaf(sc[nt][1], SCL2, slope2 * (float)(-d01)) : -3e38f;
                int d10 = i1 - j0;
                sc[nt][2] = (d10 >= 0 && d10 <= WIN)
                                ? fmaf(sc[nt][2], SCL2, slope2 * (float)(-d10)) : -3e38f;
                int d11 = d10 - 1;
                sc[nt][3] = (d11 >= 0 && d11 <= WIN)
                                ? fmaf(sc[nt][3], SCL2, slope2 * (float)(-d11)) : -3e38f;
                mx0 = fmaxf(mx0, fmaxf(sc[nt][0], sc[nt][1]));
                mx1 = fmaxf(mx1, fmaxf(sc[nt][2], sc[nt][3]));
            }
        }
        mx0 = fmaxf(mx0, __shfl_xor_sync(0xffffffffu, mx0, 1));
        mx0 = fmaxf(mx0, __shfl_xor_sync(0xffffffffu, mx0, 2));
        mx1 = fmaxf(mx1, __shfl_xor_sync(0xffffffffu, mx1, 1));
        mx1 = fmaxf(mx1, __shfl_xor_sync(0xffffffffu, mx1, 2));

        float mn0 = fmaxf(m0r, mx0), mn1 = fmaxf(m1r, mx1);
        bool upd = (mn0 > m0r) || (mn1 > m1r);
        if (__any_sync(0xffffffffu, upd)) {
            float al0 = ex2f(m0r - mn0), al1 = ex2f(m1r - mn1);  // 1.0 if no update
#pragma unroll
            for (int dt = 0; dt < 8; dt++) {
                o[dt][0] *= al0; o[dt][1] *= al0;
                o[dt][2] *= al1; o[dt][3] *= al1;
            }
            oe[0] *= al0; oe[1] *= al0;
            oe[2] *= al1; oe[3] *= al1;
        }
        m0r = mn0; m1r = mn1;

        // ---- p = exp2(sc - mn), in-register a-frags ----
        uint32_t pa[4][4];
#pragma unroll
        for (int nt = 0; nt < 8; nt++) {
            float p00 = ex2f(sc[nt][0] - mn0);
            float p01 = ex2f(sc[nt][1] - mn0);
            float p10 = ex2f(sc[nt][2] - mn1);
            float p11 = ex2f(sc[nt][3] - mn1);
            pa[nt >> 1][(nt & 1) * 2 + 0] = h2(p00, p01);
            pa[nt >> 1][(nt & 1) * 2 + 1] = h2(p10, p11);
        }

        // ---- O += P V (+ ones column accumulates row sums into oe) ----
#pragma unroll
        for (int k16 = 0; k16 < 4; k16++) {
#pragma unroll
            for (int dp = 0; dp < 4; dp++) {
                uint4 v = *(const uint4*)&Vs[(dp * 4 + k16) * 128 + lane * 4];
                mma16816(o[2 * dp + 0], pa[k16], v.x, v.y);
                mma16816(o[2 * dp + 1], pa[k16], v.z, v.w);
            }
            mma16816(oe, pa[k16], ONESH2, ONESH2);
        }
        __syncthreads();
    }

    // ---- normalize + write (l = oe row sums) ----
    float inv0 = 1.f / oe[0], inv1 = 1.f / oe[2];
    float* o0 = out + (size_t)i0 * DM + h * HD;
    float* o1 = out + (size_t)i1 * DM + h * HD;
#pragma unroll
    for (int dt = 0; dt < 8; dt++) {
        *(float2*)&o0[dt * 8 + 2 * lc] = make_float2(o[dt][0] * inv0, o[dt][1] * inv0);
        *(float2*)&o1[dt * 8 + 2 * lc] = make_float2(o[dt][2] * inv1, o[dt][3] * inv1);
    }
}

// ---------------------------------------------------------------------------
extern "C" void kernel_launch(void* const* d_in, const int* in_sizes, int n_in,
                              void* d_out, int out_size) {
    const float* x = (const float*)d_in[0];
    const float* w = (const float*)d_in[1];
    if (n_in >= 2 && in_sizes[0] == DM * NK && in_sizes[1] == S * DM) {
        const float* t = x; x = w; w = t;
    }
    float* out = (float*)d_out;

    static int attr_set = 0;
    if (!attr_set) {
        cudaFuncSetAttribute(kqv_gemm_mma, cudaFuncAttributeMaxDynamicSharedMemorySize,
                             GEMM_SMEM);
        cudaFuncSetAttribute(attn_tc, cudaFuncAttributeMaxDynamicSharedMemorySize,
                             ATTN_SMEM);
        attr_set = 1;
    }

    prep_x<<<4096, 256>>>(x);
    prep_w<<<1536, 256>>>(w);

    dim3 ggrid(NK / 128, S / 128);
    kqv_gemm_mma<<<ggrid, 256, GEMM_SMEM>>>();

    dim3 agrid(S / 64, H);
    attn_tc<<<agrid, 128, ATTN_SMEM>>>(out);
}